// round 16
// baseline (speedup 1.0000x reference)
#include <cuda_runtime.h>
#include <cuda_bf16.h>
#include <cuda_fp16.h>
#include <math.h>
#include <stdint.h>

// Problem constants
#define NB   2
#define LSEQ 2048
#define DMOD 1024
#define NHEAD 16
#define DV   64
#define DFF  4096
#define NTOK (NB*LSEQ)          // 4096 rows

// ---------------- scratch (device globals; no allocation allowed) -----------
__device__ __half g_qh [(size_t)NTOK * DMOD];
__device__ __half g_kh [(size_t)NTOK * DMOD];
__device__ __half g_vh [(size_t)NTOK * DMOD];
__device__ __half g_fcw[(size_t)DMOD * DMOD];   // [N][K] transposed fp16
__device__ __half g_w1 [(size_t)DFF * DMOD];
__device__ __half g_w2 [(size_t)DMOD * DFF];
__device__ __half g_at [(size_t)NTOK * DMOD];   // attention out (fp16)
__device__ __half g_x1f[(size_t)NTOK * DMOD];   // x1 (fp16)
__device__ __half g_ff [(size_t)NTOK * DFF];    // ffn hidden (fp16)
__device__ __half g_tmp16[(size_t)NTOK * DMOD]; // gemm out (fp16, pre-residual)
__device__ float  g_x1 [(size_t)NTOK * DMOD];
__device__ float  g_mb [(size_t)NB * LSEQ];     // additive mask bias (0 / -1e4)

// ========================= helpers ==========================================
__device__ __forceinline__ uint32_t smem_u32(const void* p) {
    uint32_t a;
    asm("{ .reg .u64 t; cvta.to.shared.u64 t, %1; cvt.u32.u64 %0, t; }"
        : "=r"(a) : "l"(p));
    return a;
}
#define SWZ(off)   ((uint32_t)(off) ^ ((((uint32_t)(off)) >> 3) & 0x70u))
#define SWZ64(off) ((uint32_t)(off) ^ ((((uint32_t)(off)) >> 3) & 0x30u))
#define CP16(dst, src) \
    asm volatile("cp.async.cg.shared.global [%0], [%1], 16;" :: "r"(dst), "l"(src))
#define CP_COMMIT() asm volatile("cp.async.commit_group;")
#define CP_WAIT4()  asm volatile("cp.async.wait_group 4;")
#define CP_WAIT3()  asm volatile("cp.async.wait_group 3;")
#define CP_WAIT2()  asm volatile("cp.async.wait_group 2;")
#define CP_WAIT1()  asm volatile("cp.async.wait_group 1;")
#define CP_WAIT0()  asm volatile("cp.async.wait_group 0;")

__device__ __forceinline__ void ldsm4(uint32_t r[4], uint32_t a) {
    asm volatile("ldmatrix.sync.aligned.m8n8.x4.shared.b16 {%0,%1,%2,%3}, [%4];"
        : "=r"(r[0]), "=r"(r[1]), "=r"(r[2]), "=r"(r[3]) : "r"(a));
}
__device__ __forceinline__ void ldsm4t(uint32_t r[4], uint32_t a) {
    asm volatile("ldmatrix.sync.aligned.m8n8.x4.trans.shared.b16 {%0,%1,%2,%3}, [%4];"
        : "=r"(r[0]), "=r"(r[1]), "=r"(r[2]), "=r"(r[3]) : "r"(a));
}
// fp16 HMMA, fp32 accumulate
__device__ __forceinline__ void mma16816(float c[4], const uint32_t a[4], const uint32_t b[2]) {
    asm volatile(
        "mma.sync.aligned.m16n8k16.row.col.f32.f16.f16.f32 "
        "{%0,%1,%2,%3}, {%4,%5,%6,%7}, {%8,%9}, {%0,%1,%2,%3};"
        : "+f"(c[0]), "+f"(c[1]), "+f"(c[2]), "+f"(c[3])
        : "r"(a[0]), "r"(a[1]), "r"(a[2]), "r"(a[3]), "r"(b[0]), "r"(b[1]));
}
__device__ __forceinline__ uint32_t packh2(float lo, float hi) {
    uint32_t r;
    asm("cvt.rn.f16x2.f32 %0, %1, %2;" : "=r"(r) : "f"(hi), "f"(lo));
    return r;
}
// one MUFU op for TWO exponentials (fp16x2, base-2)
__device__ __forceinline__ uint32_t ex2h2(uint32_t x) {
    uint32_t r;
    asm("ex2.approx.f16x2 %0, %1;" : "=r"(r) : "r"(x));
    return r;
}

// ===================== unified prep kernel ==================================
//   [0, 4096)        conv_qkv  (fp32 -> fp16, Q scaled)
//   [4096, 5120)     fc_w  transpose (K=1024, N=1024)
//   [5120, 9216)     ff_w1 transpose (K=1024, N=4096)
//   [9216, 13312)    ff_w2 transpose (K=4096, N=1024)
//   [13312, 13328)   mask -> additive float bias
#define PREP_BLOCKS 13328

__device__ __forceinline__ void wT_task(const float* __restrict__ W,
                                        __half* __restrict__ Th,
                                        int K, int N, int bx, int by, int tid)
{
    __shared__ float t[32][33];                    // t[k][n]
    const int n0 = bx*32, k0 = by*32;
    const int tx = tid & 31, ty = tid >> 5;        // 32 x 8
    #pragma unroll
    for (int i = 0; i < 4; i++)
        t[ty + 8*i][tx] = W[(size_t)(k0 + ty + 8*i)*N + n0 + tx];
    __syncthreads();
    const int n  = 4*ty + (tx >> 3);
    const int kg = tx & 7;
    uint32_t h01 = packh2(t[kg*4+0][n], t[kg*4+1][n]);
    uint32_t h23 = packh2(t[kg*4+2][n], t[kg*4+3][n]);
    size_t o = (size_t)(n0 + n)*K + k0 + kg*4;
    *(uint2*)(Th + o) = make_uint2(h01, h23);
}

__global__ void prep_all(const float4* __restrict__ Q, const float4* __restrict__ K4,
                         const float4* __restrict__ V4, const int* __restrict__ mask,
                         const float* __restrict__ fc_w, const float* __restrict__ ff_w1,
                         const float* __restrict__ ff_w2,
                         __half* __restrict__ qh, __half* __restrict__ kh,
                         __half* __restrict__ vh, __half* __restrict__ fcw,
                         __half* __restrict__ w1, __half* __restrict__ w2,
                         float* __restrict__ mb)
{
    const int b = blockIdx.x;
    const int tid = threadIdx.x;
    if (b < 4096) {
        const size_t i = (size_t)b * 256 + tid;
        const float QS = 1.4426950408889634f / 32.0f;
        float4 q = Q[i];
        *(uint2*)(qh + i*4) = make_uint2(packh2(q.x*QS, q.y*QS), packh2(q.z*QS, q.w*QS));
        float4 k = K4[i];
        *(uint2*)(kh + i*4) = make_uint2(packh2(k.x, k.y), packh2(k.z, k.w));
        float4 v = V4[i];
        *(uint2*)(vh + i*4) = make_uint2(packh2(v.x, v.y), packh2(v.z, v.w));
    } else if (b < 5120) {
        int idx = b - 4096;
        wT_task(fc_w, fcw, DMOD, DMOD, idx & 31, idx >> 5, tid);
    } else if (b < 9216) {
        int idx = b - 5120;
        wT_task(ff_w1, w1, DMOD, DFF, idx & 127, idx >> 7, tid);
    } else if (b < 13312) {
        int idx = b - 9216;
        wT_task(ff_w2, w2, DFF, DMOD, idx & 31, idx >> 5, tid);
    } else {
        int i = (b - 13312) * 256 + tid;
        mb[i] = mask[i] ? 0.f : -1e4f;
    }
}

// ======= unified 6-stage cp.async fp16 GEMM, 128x128 tile, 2 CTAs/SM ========
static constexpr int G_STAGE = 16384;
static constexpr int GSMEM   = 6 * G_STAGE;    // 96KB

template<int RELU>
__global__ void __launch_bounds__(256, 2)
gemm_cp(const __half* __restrict__ A, const __half* __restrict__ B,
        const float* __restrict__ bias, __half* __restrict__ O16,
        int M, int N, int K)
{
    extern __shared__ __align__(1024) char sm[];
    const uint32_t smb = smem_u32(sm);
    const int tid = threadIdx.x, lane = tid & 31, wid = tid >> 5;
    const int wm = wid >> 2, wn = wid & 3;           // 2m x 4n
    const int bx = blockIdx.x, by = blockIdx.y;
    const int NC = K >> 5;

    auto issue = [&](int kc) {
        const uint32_t sb = smb + (kc % 6) * G_STAGE;
        #pragma unroll
        for (int j = 0; j < 2; j++) {
            int idx = tid + j*256, row = idx >> 2, part = idx & 3;
            uint32_t d = SWZ64(row*64 + part*16);
            size_t goA = (size_t)(by*128 + row)*K + kc*32 + part*8;
            size_t goB = (size_t)(bx*128 + row)*K + kc*32 + part*8;
            CP16(sb + d,        A + goA);
            CP16(sb + 8192 + d, B + goB);
        }
        CP_COMMIT();
    };

    float acc[4][4][4] = {};

    issue(0); issue(1); issue(2); issue(3); issue(4);

    for (int kc = 0; kc < NC; kc++) {
        if (kc + 4 < NC)      CP_WAIT4();
        else if (kc + 3 < NC) CP_WAIT3();
        else if (kc + 2 < NC) CP_WAIT2();
        else if (kc + 1 < NC) CP_WAIT1();
        else                  CP_WAIT0();
        __syncthreads();
        if (kc + 5 < NC) issue(kc + 5);

        const uint32_t base = smb + (kc % 6) * G_STAGE;
        #pragma unroll
        for (int ks = 0; ks < 2; ks++) {
            uint32_t ah[4][4];
            #pragma unroll
            for (int i = 0; i < 4; i++) {
                uint32_t off = SWZ64((wm*64 + i*16 + (lane&15))*64 + ks*32 + (lane>>4)*16);
                ldsm4(ah[i], base + off);
            }
            #pragma unroll
            for (int jj = 0; jj < 2; jj++) {
                const int m = lane >> 3;
                uint32_t off = SWZ64((wn*32 + jj*16 + (m>>1)*8 + (lane&7))*64
                                     + ks*32 + (m&1)*16);
                uint32_t tb[4];
                ldsm4(tb, base + 8192 + off);
                uint32_t bh0[2] = {tb[0], tb[1]}, bh1[2] = {tb[2], tb[3]};
                #pragma unroll
                for (int i = 0; i < 4; i++) {
                    mma16816(acc[i][jj*2+0], ah[i], bh0);
                    mma16816(acc[i][jj*2+1], ah[i], bh1);
                }
            }
        }
    }

    #pragma unroll
    for (int i = 0; i < 4; i++) {
        int row0 = by*128 + wm*64 + i*16 + (lane >> 2);
        int row1 = row0 + 8;
        #pragma unroll
        for (int j = 0; j < 4; j++) {
            int col = bx*128 + wn*32 + j*8 + (lane & 3)*2;
            float2 bv = *(const float2*)(bias + col);
            float v0 = acc[i][j][0] + bv.x, v1 = acc[i][j][1] + bv.y;
            float v2 = acc[i][j][2] + bv.x, v3 = acc[i][j][3] + bv.y;
            if (RELU) {
                v0 = fmaxf(v0, 0.f); v1 = fmaxf(v1, 0.f);
                v2 = fmaxf(v2, 0.f); v3 = fmaxf(v3, 0.f);
            }
            *(uint32_t*)(O16 + (size_t)row0*N + col) = packh2(v0, v1);
            *(uint32_t*)(O16 + (size_t)row1*N + col) = packh2(v2, v3);
        }
    }
}

// ============ 2-stage cp.async flash attention, 2 CTAs/SM ===================
static constexpr int A_STG   = 32768;
static constexpr int A_MASK0 = 16384 + 2 * A_STG;       // 81920
static constexpr int ASMEM   = A_MASK0 + 2 * 512;       // 82944

__global__ void __launch_bounds__(256, 2)
attn_cp(const __half* __restrict__ Qh, const __half* __restrict__ Kh,
        const __half* __restrict__ Vh, const float* __restrict__ mb,
        __half* __restrict__ O)
{
    extern __shared__ __align__(1024) char sm[];
    const uint32_t smb = smem_u32(sm);
    const int tid = threadIdx.x, lane = tid & 31, wid = tid >> 5;
    const int qb0 = blockIdx.x * 128, h = blockIdx.y, n = blockIdx.z;
    const int NT = LSEQ / 128;

    auto issueKV = [&](int kt) {
        const int s = kt & 1;
        const uint32_t kb = smb + 16384 + s * A_STG;
        const uint32_t vb = kb + 16384;
        #pragma unroll
        for (int j = 0; j < 4; j++) {
            int idx = tid + j*256, row = idx >> 3, part = idx & 7;
            uint32_t d = SWZ(row*128 + part*16);
            size_t go = (size_t)(n*LSEQ + kt*128 + row)*DMOD + h*64 + part*8;
            CP16(kb + d, Kh + go);
            CP16(vb + d, Vh + go);
        }
        if (tid < 32)
            CP16(smb + A_MASK0 + s*512 + tid*16, mb + n*LSEQ + kt*128 + tid*4);
        CP_COMMIT();
    };

    #pragma unroll
    for (int j = 0; j < 4; j++) {
        int idx = tid + j*256, row = idx >> 3, part = idx & 7;
        CP16(smb + SWZ(row*128 + part*16),
             Qh + (size_t)(n*LSEQ + qb0 + row)*DMOD + h*64 + part*8);
    }
    issueKV(0);

    uint32_t qa[4][4];
    float accO[8][4] = {};
    float l0 = 0.f, l1 = 0.f;

    for (int kt = 0; kt < NT; kt++) {
        if (kt + 1 < NT) { issueKV(kt + 1); CP_WAIT1(); }
        else             { CP_WAIT0(); }
        __syncthreads();
        if (kt == 0) {
            #pragma unroll
            for (int ks = 0; ks < 4; ks++)
                ldsm4(qa[ks], smb + SWZ((wid*16 + (lane&15))*128 + ks*32 + (lane>>4)*16));
        }
        const int s = kt & 1;
        const uint32_t kb = smb + 16384 + s * A_STG;
        const uint32_t vb = kb + 16384;
        const float* smMB = (const float*)(sm + A_MASK0 + s*512);

        #pragma unroll
        for (int hf = 0; hf < 2; hf++) {
            float S[8][4] = {};
            #pragma unroll
            for (int ks = 0; ks < 4; ks++) {
                #pragma unroll
                for (int jj = 0; jj < 4; jj++) {
                    const int m = lane >> 3;
                    uint32_t off = SWZ((hf*64 + jj*16 + (m>>1)*8 + (lane&7))*128
                                       + ks*32 + (m&1)*16);
                    uint32_t t[4]; ldsm4(t, kb + off);
                    uint32_t b0[2] = {t[0], t[1]}, b1[2] = {t[2], t[3]};
                    mma16816(S[jj*2+0], qa[ks], b0);
                    mma16816(S[jj*2+1], qa[ks], b1);
                }
            }
            uint32_t pa[4][4];
            #pragma unroll
            for (int j = 0; j < 8; j++) {
                int c0 = hf*64 + j*8 + (lane & 3)*2;
                float2 mbv = *(const float2*)(smMB + c0);
                // pack masked scores to fp16x2, one MUFU per pair
                uint32_t p01 = ex2h2(packh2(S[j][0] + mbv.x, S[j][1] + mbv.y));
                uint32_t p23 = ex2h2(packh2(S[j][2] + mbv.x, S[j][3] + mbv.y));
                float2 f01 = __half22float2(*(__half2*)&p01);
                float2 f23 = __half22float2(*(__half2*)&p23);
                l0 += f01.x + f01.y;
                l1 += f23.x + f23.y;
                int ks2 = j >> 1;
                if ((j & 1) == 0) { pa[ks2][0] = p01; pa[ks2][1] = p23; }
                else              { pa[ks2][2] = p01; pa[ks2][3] = p23; }
            }
            #pragma unroll
            for (int kss = 0; kss < 4; kss++) {
                #pragma unroll
                for (int p = 0; p < 4; p++) {
                    uint32_t off = SWZ((hf*64 + kss*16 + (lane&7) + ((lane&8) ? 8 : 0))*128
                                       + (2*p + (lane>>4))*16);
                    uint32_t t[4]; ldsm4t(t, vb + off);
                    uint32_t b0[2] = {t[0], t[1]}, b1[2] = {t[2], t[3]};
                    mma16816(accO[2*p+0], pa[kss], b0);
                    mma16816(accO[2*p+1], pa[kss], b1);
                }
            }
        }
        __syncthreads();
    }

    l0 += __shfl_xor_sync(~0u, l0, 1); l0 += __shfl_xor_sync(~0u, l0, 2);
    l1 += __shfl_xor_sync(~0u, l1, 1); l1 += __shfl_xor_sync(~0u, l1, 2);
    float i0 = 1.f / l0, i1 = 1.f / l1;
    int r0 = qb0 + wid*16 + (lane >> 2), r1 = r0 + 8;
    #pragma unroll
    for (int j = 0; j < 8; j++) {
        int col = h*64 + j*8 + (lane & 3)*2;
        *(uint32_t*)(O + (size_t)(n*LSEQ + r0)*DMOD + col) = packh2(accO[j][0]*i0, accO[j][1]*i0);
        *(uint32_t*)(O + (size_t)(n*LSEQ + r1)*DMOD + col) = packh2(accO[j][2]*i1, accO[j][3]*i1);
    }
}

// ===================== fused residual + LayerNorm ===========================
template<bool EMIT16>
__global__ void ln_kernel(const __half* __restrict__ x, const float* __restrict__ res,
                          const float* __restrict__ g, const float* __restrict__ b,
                          float* __restrict__ out, __half* __restrict__ o16)
{
    const int row = blockIdx.x;
    const int tid = threadIdx.x;           // 256
    const uint2 xh = ((const uint2*)(x + (size_t)row*DMOD))[tid];
    const float4 rv = ((const float4*)(res + (size_t)row*DMOD))[tid];
    __half2 x01 = *(const __half2*)&xh.x;
    __half2 x23 = *(const __half2*)&xh.y;
    float v0 = __half2float(__low2half(x01))  + rv.x;
    float v1 = __half2float(__high2half(x01)) + rv.y;
    float v2 = __half2float(__low2half(x23))  + rv.z;
    float v3 = __half2float(__high2half(x23)) + rv.w;

    float s  = v0 + v1 + v2 + v3;
    float ss = v0*v0 + v1*v1 + v2*v2 + v3*v3;

    __shared__ float red0[8], red1[8];
    #pragma unroll
    for (int o = 16; o > 0; o >>= 1) {
        s  += __shfl_xor_sync(0xFFFFFFFFu, s,  o);
        ss += __shfl_xor_sync(0xFFFFFFFFu, ss, o);
    }
    if ((tid & 31) == 0) { red0[tid>>5] = s; red1[tid>>5] = ss; }
    __syncthreads();
    float S = 0.f, SS = 0.f;
    #pragma unroll
    for (int w = 0; w < 8; w++) { S += red0[w]; SS += red1[w]; }

    const float mu   = S * (1.0f/DMOD);
    const float var  = SS * (1.0f/DMOD) - mu*mu;
    const float rstd = rsqrtf(var + 1e-5f);

    const float4 gv = ((const float4*)g)[tid];
    const float4 bv = ((const float4*)b)[tid];
    float4 o;
    o.x = (v0 - mu)*rstd*gv.x + bv.x;
    o.y = (v1 - mu)*rstd*gv.y + bv.y;
    o.z = (v2 - mu)*rstd*gv.z + bv.z;
    o.w = (v3 - mu)*rstd*gv.w + bv.w;
    ((float4*)(out + (size_t)row*DMOD))[tid] = o;
    if (EMIT16) {
        *(uint2*)(o16 + (size_t)row*DMOD + tid*4) =
            make_uint2(packh2(o.x, o.y), packh2(o.z, o.w));
    }
}

// ================================ launch ====================================
extern "C" void kernel_launch(void* const* d_in, const int* in_sizes, int n_in,
                              void* d_out, int out_size)
{
    const float* queries = (const float*)d_in[0];
    const float* keys    = (const float*)d_in[1];
    const float* values  = (const float*)d_in[2];
    const int*   mask    = (const int*  )d_in[3];
    const float* fc_w    = (const float*)d_in[4];
    const float* fc_b    = (const float*)d_in[5];
    const float* ln1_g   = (const float*)d_in[6];
    const float* ln1_b   = (const float*)d_in[7];
    const float* ff_w1   = (const float*)d_in[8];
    const float* ff_b1   = (const float*)d_in[9];
    const float* ff_w2   = (const float*)d_in[10];
    const float* ff_b2   = (const float*)d_in[11];
    const float* ln2_g   = (const float*)d_in[12];
    const float* ln2_b   = (const float*)d_in[13];
    float* out = (float*)d_out;

    __half *qh, *kh, *vh, *fcw, *w1, *w2, *at, *x1f, *ff, *tmp16;
    float *x1, *mb;
    cudaGetSymbolAddress((void**)&qh,    g_qh);
    cudaGetSymbolAddress((void**)&kh,    g_kh);
    cudaGetSymbolAddress((void**)&vh,    g_vh);
    cudaGetSymbolAddress((void**)&fcw,   g_fcw);
    cudaGetSymbolAddress((void**)&w1,    g_w1);
    cudaGetSymbolAddress((void**)&w2,    g_w2);
    cudaGetSymbolAddress((void**)&at,    g_at);
    cudaGetSymbolAddress((void**)&x1f,   g_x1f);
    cudaGetSymbolAddress((void**)&ff,    g_ff);
    cudaGetSymbolAddress((void**)&tmp16, g_tmp16);
    cudaGetSymbolAddress((void**)&x1,    g_x1);
    cudaGetSymbolAddress((void**)&mb,    g_mb);

    cudaFuncSetAttribute(gemm_cp<0>, cudaFuncAttributeMaxDynamicSharedMemorySize, GSMEM);
    cudaFuncSetAttribute(gemm_cp<1>, cudaFuncAttributeMaxDynamicSharedMemorySize, GSMEM);
    cudaFuncSetAttribute(attn_cp,    cudaFuncAttributeMaxDynamicSharedMemorySize, ASMEM);

    // 0) all preps in one launch
    prep_all<<<PREP_BLOCKS, 256>>>((const float4*)queries, (const float4*)keys,
                                   (const float4*)values, mask, fc_w, ff_w1, ff_w2,
                                   qh, kh, vh, fcw, w1, w2, mb);

    // 1) attention -> fp16
    attn_cp<<<dim3(LSEQ/128, NHEAD, NB), 256, ASMEM>>>(qh, kh, vh, mb, at);
    // 2) fc projection -> fp16 tmp
    gemm_cp<0><<<dim3(DMOD/128, NTOK/128), 256, GSMEM>>>(at, fcw, fc_b,
                                                         tmp16, NTOK, DMOD, DMOD);
    // 3) x1 = LN(tmp + queries) -> fp32 + fp16
    ln_kernel<true><<<NTOK, 256>>>(tmp16, queries, ln1_g, ln1_b, x1, x1f);
    // 4) ff = relu(x1 @ w1 + b1) -> fp16
    gemm_cp<1><<<dim3(DFF/128, NTOK/128), 256, GSMEM>>>(x1f, w1, ff_b1,
                                                        ff, NTOK, DFF, DMOD);
    // 5) tmp = ff @ w2 + b2 -> fp16
    gemm_cp<0><<<dim3(DMOD/128, NTOK/128), 256, GSMEM>>>(ff, w2, ff_b2,
                                                         tmp16, NTOK, DMOD, DFF);
    // 6) out = LN(tmp + x1)
    ln_kernel<false><<<NTOK, 256>>>(tmp16, x1, ln2_g, ln2_b, out, nullptr);
}

// round 17
// speedup vs baseline: 1.4841x; 1.4841x over previous
#include <cuda_runtime.h>
#include <cuda_bf16.h>
#include <cuda_fp16.h>
#include <math.h>
#include <stdint.h>

// Problem constants
#define NB   2
#define LSEQ 2048
#define DMOD 1024
#define NHEAD 16
#define DV   64
#define DFF  4096
#define NTOK (NB*LSEQ)          // 4096 rows

// ---------------- scratch (device globals; no allocation allowed) -----------
__device__ __half g_qh [(size_t)NTOK * DMOD];
__device__ __half g_kh [(size_t)NTOK * DMOD];
__device__ __half g_vh [(size_t)NTOK * DMOD];
__device__ __half g_fcw[(size_t)DMOD * DMOD];   // [N][K] transposed fp16
__device__ __half g_w1 [(size_t)DFF * DMOD];
__device__ __half g_w2 [(size_t)DMOD * DFF];
__device__ __half g_at [(size_t)NTOK * DMOD];   // attention out (fp16)
__device__ __half g_x1f[(size_t)NTOK * DMOD];   // x1 (fp16)
__device__ __half g_ff [(size_t)NTOK * DFF];    // ffn hidden (fp16)
__device__ __half g_tmp16[(size_t)NTOK * DMOD]; // gemm out (fp16, pre-residual)
__device__ float  g_x1 [(size_t)NTOK * DMOD];
__device__ float  g_mb [(size_t)NB * LSEQ];     // additive mask bias (0 / -1e4)

// ========================= helpers ==========================================
__device__ __forceinline__ uint32_t smem_u32(const void* p) {
    uint32_t a;
    asm("{ .reg .u64 t; cvta.to.shared.u64 t, %1; cvt.u32.u64 %0, t; }"
        : "=r"(a) : "l"(p));
    return a;
}
#define SWZ(off)   ((uint32_t)(off) ^ ((((uint32_t)(off)) >> 3) & 0x70u))
#define SWZ64(off) ((uint32_t)(off) ^ ((((uint32_t)(off)) >> 3) & 0x30u))
#define CP16(dst, src) \
    asm volatile("cp.async.cg.shared.global [%0], [%1], 16;" :: "r"(dst), "l"(src))
#define CP_COMMIT() asm volatile("cp.async.commit_group;")
#define CP_WAIT4()  asm volatile("cp.async.wait_group 4;")
#define CP_WAIT3()  asm volatile("cp.async.wait_group 3;")
#define CP_WAIT2()  asm volatile("cp.async.wait_group 2;")
#define CP_WAIT1()  asm volatile("cp.async.wait_group 1;")
#define CP_WAIT0()  asm volatile("cp.async.wait_group 0;")

__device__ __forceinline__ void ldsm4(uint32_t r[4], uint32_t a) {
    asm volatile("ldmatrix.sync.aligned.m8n8.x4.shared.b16 {%0,%1,%2,%3}, [%4];"
        : "=r"(r[0]), "=r"(r[1]), "=r"(r[2]), "=r"(r[3]) : "r"(a));
}
__device__ __forceinline__ void ldsm4t(uint32_t r[4], uint32_t a) {
    asm volatile("ldmatrix.sync.aligned.m8n8.x4.trans.shared.b16 {%0,%1,%2,%3}, [%4];"
        : "=r"(r[0]), "=r"(r[1]), "=r"(r[2]), "=r"(r[3]) : "r"(a));
}
// fp16 HMMA, fp32 accumulate
__device__ __forceinline__ void mma16816(float c[4], const uint32_t a[4], const uint32_t b[2]) {
    asm volatile(
        "mma.sync.aligned.m16n8k16.row.col.f32.f16.f16.f32 "
        "{%0,%1,%2,%3}, {%4,%5,%6,%7}, {%8,%9}, {%0,%1,%2,%3};"
        : "+f"(c[0]), "+f"(c[1]), "+f"(c[2]), "+f"(c[3])
        : "r"(a[0]), "r"(a[1]), "r"(a[2]), "r"(a[3]), "r"(b[0]), "r"(b[1]));
}
__device__ __forceinline__ uint32_t packh2(float lo, float hi) {
    uint32_t r;
    asm("cvt.rn.f16x2.f32 %0, %1, %2;" : "=r"(r) : "f"(hi), "f"(lo));
    return r;
}
// single-MUFU 2^x (scores already in log2 domain; -1e4 -> 0 naturally)
__device__ __forceinline__ float ex2(float x) {
    float r;
    asm("ex2.approx.f32 %0, %1;" : "=f"(r) : "f"(x));
    return r;
}

// ===================== prep kernels =========================================
// prep_qkv: [0,4096) qkv convert, [4096,4112) mask -> additive bias
__global__ void prep_qkv(const float4* __restrict__ Q, const float4* __restrict__ K4,
                         const float4* __restrict__ V4, const int* __restrict__ mask,
                         __half* __restrict__ qh, __half* __restrict__ kh,
                         __half* __restrict__ vh, float* __restrict__ mb)
{
    const int b = blockIdx.x;
    const int tid = threadIdx.x;
    if (b < 4096) {
        const size_t i = (size_t)b * 256 + tid;
        const float QS = 1.4426950408889634f / 32.0f;
        float4 q = Q[i];
        *(uint2*)(qh + i*4) = make_uint2(packh2(q.x*QS, q.y*QS), packh2(q.z*QS, q.w*QS));
        float4 k = K4[i];
        *(uint2*)(kh + i*4) = make_uint2(packh2(k.x, k.y), packh2(k.z, k.w));
        float4 v = V4[i];
        *(uint2*)(vh + i*4) = make_uint2(packh2(v.x, v.y), packh2(v.z, v.w));
    } else {
        int i = (b - 4096) * 256 + tid;
        mb[i] = mask[i] ? 0.f : -1e4f;
    }
}

// prep_w: weight transposes only
__device__ __forceinline__ void wT_task(const float* __restrict__ W,
                                        __half* __restrict__ Th,
                                        int K, int N, int bx, int by, int tid)
{
    __shared__ float t[32][33];                    // t[k][n]
    const int n0 = bx*32, k0 = by*32;
    const int tx = tid & 31, ty = tid >> 5;        // 32 x 8
    #pragma unroll
    for (int i = 0; i < 4; i++)
        t[ty + 8*i][tx] = W[(size_t)(k0 + ty + 8*i)*N + n0 + tx];
    __syncthreads();
    const int n  = 4*ty + (tx >> 3);
    const int kg = tx & 7;
    uint32_t h01 = packh2(t[kg*4+0][n], t[kg*4+1][n]);
    uint32_t h23 = packh2(t[kg*4+2][n], t[kg*4+3][n]);
    size_t o = (size_t)(n0 + n)*K + k0 + kg*4;
    *(uint2*)(Th + o) = make_uint2(h01, h23);
}

__global__ void prep_w(const float* __restrict__ fc_w, const float* __restrict__ ff_w1,
                       const float* __restrict__ ff_w2,
                       __half* __restrict__ fcw, __half* __restrict__ w1,
                       __half* __restrict__ w2)
{
    const int b = blockIdx.x;
    const int tid = threadIdx.x;
    if (b < 1024) {
        wT_task(fc_w, fcw, DMOD, DMOD, b & 31, b >> 5, tid);
    } else if (b < 5120) {
        int idx = b - 1024;                         // 4096 blocks: 128 x 32
        wT_task(ff_w1, w1, DMOD, DFF, idx & 127, idx >> 7, tid);
    } else {
        int idx = b - 5120;                         // 4096 blocks: 32 x 128
        wT_task(ff_w2, w2, DFF, DMOD, idx & 31, idx >> 5, tid);
    }
}

// ======= unified 6-stage cp.async fp16 GEMM, 128x128 tile, 2 CTAs/SM ========
static constexpr int G_STAGE = 16384;
static constexpr int GSMEM   = 6 * G_STAGE;    // 96KB

template<int RELU>
__global__ void __launch_bounds__(256, 2)
gemm_cp(const __half* __restrict__ A, const __half* __restrict__ B,
        const float* __restrict__ bias, __half* __restrict__ O16,
        int M, int N, int K)
{
    extern __shared__ __align__(1024) char sm[];
    const uint32_t smb = smem_u32(sm);
    const int tid = threadIdx.x, lane = tid & 31, wid = tid >> 5;
    const int wm = wid >> 2, wn = wid & 3;           // 2m x 4n
    const int bx = blockIdx.x, by = blockIdx.y;
    const int NC = K >> 5;

    auto issue = [&](int kc) {
        const uint32_t sb = smb + (kc % 6) * G_STAGE;
        #pragma unroll
        for (int j = 0; j < 2; j++) {
            int idx = tid + j*256, row = idx >> 2, part = idx & 3;
            uint32_t d = SWZ64(row*64 + part*16);
            size_t goA = (size_t)(by*128 + row)*K + kc*32 + part*8;
            size_t goB = (size_t)(bx*128 + row)*K + kc*32 + part*8;
            CP16(sb + d,        A + goA);
            CP16(sb + 8192 + d, B + goB);
        }
        CP_COMMIT();
    };

    float acc[4][4][4] = {};

    issue(0); issue(1); issue(2); issue(3); issue(4);

    for (int kc = 0; kc < NC; kc++) {
        if (kc + 4 < NC)      CP_WAIT4();
        else if (kc + 3 < NC) CP_WAIT3();
        else if (kc + 2 < NC) CP_WAIT2();
        else if (kc + 1 < NC) CP_WAIT1();
        else                  CP_WAIT0();
        __syncthreads();
        if (kc + 5 < NC) issue(kc + 5);

        const uint32_t base = smb + (kc % 6) * G_STAGE;
        #pragma unroll
        for (int ks = 0; ks < 2; ks++) {
            uint32_t ah[4][4];
            #pragma unroll
            for (int i = 0; i < 4; i++) {
                uint32_t off = SWZ64((wm*64 + i*16 + (lane&15))*64 + ks*32 + (lane>>4)*16);
                ldsm4(ah[i], base + off);
            }
            #pragma unroll
            for (int jj = 0; jj < 2; jj++) {
                const int m = lane >> 3;
                uint32_t off = SWZ64((wn*32 + jj*16 + (m>>1)*8 + (lane&7))*64
                                     + ks*32 + (m&1)*16);
                uint32_t tb[4];
                ldsm4(tb, base + 8192 + off);
                uint32_t bh0[2] = {tb[0], tb[1]}, bh1[2] = {tb[2], tb[3]};
                #pragma unroll
                for (int i = 0; i < 4; i++) {
                    mma16816(acc[i][jj*2+0], ah[i], bh0);
                    mma16816(acc[i][jj*2+1], ah[i], bh1);
                }
            }
        }
    }

    #pragma unroll
    for (int i = 0; i < 4; i++) {
        int row0 = by*128 + wm*64 + i*16 + (lane >> 2);
        int row1 = row0 + 8;
        #pragma unroll
        for (int j = 0; j < 4; j++) {
            int col = bx*128 + wn*32 + j*8 + (lane & 3)*2;
            float2 bv = *(const float2*)(bias + col);
            float v0 = acc[i][j][0] + bv.x, v1 = acc[i][j][1] + bv.y;
            float v2 = acc[i][j][2] + bv.x, v3 = acc[i][j][3] + bv.y;
            if (RELU) {
                v0 = fmaxf(v0, 0.f); v1 = fmaxf(v1, 0.f);
                v2 = fmaxf(v2, 0.f); v3 = fmaxf(v3, 0.f);
            }
            *(uint32_t*)(O16 + (size_t)row0*N + col) = packh2(v0, v1);
            *(uint32_t*)(O16 + (size_t)row1*N + col) = packh2(v2, v3);
        }
    }
}

// ============ 2-stage cp.async flash attention, 2 CTAs/SM ===================
static constexpr int A_STG   = 32768;
static constexpr int A_MASK0 = 16384 + 2 * A_STG;       // 81920
static constexpr int ASMEM   = A_MASK0 + 2 * 512;       // 82944

__global__ void __launch_bounds__(256, 2)
attn_cp(const __half* __restrict__ Qh, const __half* __restrict__ Kh,
        const __half* __restrict__ Vh, const float* __restrict__ mb,
        __half* __restrict__ O)
{
    extern __shared__ __align__(1024) char sm[];
    const uint32_t smb = smem_u32(sm);
    const int tid = threadIdx.x, lane = tid & 31, wid = tid >> 5;
    const int qb0 = blockIdx.x * 128, h = blockIdx.y, n = blockIdx.z;
    const int NT = LSEQ / 128;

    auto issueKV = [&](int kt) {
        const int s = kt & 1;
        const uint32_t kb = smb + 16384 + s * A_STG;
        const uint32_t vb = kb + 16384;
        #pragma unroll
        for (int j = 0; j < 4; j++) {
            int idx = tid + j*256, row = idx >> 3, part = idx & 7;
            uint32_t d = SWZ(row*128 + part*16);
            size_t go = (size_t)(n*LSEQ + kt*128 + row)*DMOD + h*64 + part*8;
            CP16(kb + d, Kh + go);
            CP16(vb + d, Vh + go);
        }
        if (tid < 32)
            CP16(smb + A_MASK0 + s*512 + tid*16, mb + n*LSEQ + kt*128 + tid*4);
        CP_COMMIT();
    };

    #pragma unroll
    for (int j = 0; j < 4; j++) {
        int idx = tid + j*256, row = idx >> 3, part = idx & 7;
        CP16(smb + SWZ(row*128 + part*16),
             Qh + (size_t)(n*LSEQ + qb0 + row)*DMOD + h*64 + part*8);
    }
    issueKV(0);

    uint32_t qa[4][4];
    float accO[8][4] = {};
    float l0 = 0.f, l1 = 0.f;

    for (int kt = 0; kt < NT; kt++) {
        if (kt + 1 < NT) { issueKV(kt + 1); CP_WAIT1(); }
        else             { CP_WAIT0(); }
        __syncthreads();
        if (kt == 0) {
            #pragma unroll
            for (int ks = 0; ks < 4; ks++)
                ldsm4(qa[ks], smb + SWZ((wid*16 + (lane&15))*128 + ks*32 + (lane>>4)*16));
        }
        const int s = kt & 1;
        const uint32_t kb = smb + 16384 + s * A_STG;
        const uint32_t vb = kb + 16384;
        const float* smMB = (const float*)(sm + A_MASK0 + s*512);

        #pragma unroll
        for (int hf = 0; hf < 2; hf++) {
            float S[8][4] = {};
            #pragma unroll
            for (int ks = 0; ks < 4; ks++) {
                #pragma unroll
                for (int jj = 0; jj < 4; jj++) {
                    const int m = lane >> 3;
                    uint32_t off = SWZ((hf*64 + jj*16 + (m>>1)*8 + (lane&7))*128
                                       + ks*32 + (m&1)*16);
                    uint32_t t[4]; ldsm4(t, kb + off);
                    uint32_t b0[2] = {t[0], t[1]}, b1[2] = {t[2], t[3]};
                    mma16816(S[jj*2+0], qa[ks], b0);
                    mma16816(S[jj*2+1], qa[ks], b1);
                }
            }
            uint32_t pa[4][4];
            #pragma unroll
            for (int j = 0; j < 8; j++) {
                int c0 = hf*64 + j*8 + (lane & 3)*2;
                float2 mbv = *(const float2*)(smMB + c0);
                float p0 = ex2(S[j][0] + mbv.x), p1 = ex2(S[j][1] + mbv.y);
                float p2 = ex2(S[j][2] + mbv.x), p3 = ex2(S[j][3] + mbv.y);
                l0 += p0 + p1; l1 += p2 + p3;
                int ks2 = j >> 1;
                if ((j & 1) == 0) { pa[ks2][0] = packh2(p0, p1); pa[ks2][1] = packh2(p2, p3); }
                else              { pa[ks2][2] = packh2(p0, p1); pa[ks2][3] = packh2(p2, p3); }
            }
            #pragma unroll
            for (int kss = 0; kss < 4; kss++) {
                #pragma unroll
                for (int p = 0; p < 4; p++) {
                    uint32_t off = SWZ((hf*64 + kss*16 + (lane&7) + ((lane&8) ? 8 : 0))*128
                                       + (2*p + (lane>>4))*16);
                    uint32_t t[4]; ldsm4t(t, vb + off);
                    uint32_t b0[2] = {t[0], t[1]}, b1[2] = {t[2], t[3]};
                    mma16816(accO[2*p+0], pa[kss], b0);
                    mma16816(accO[2*p+1], pa[kss], b1);
                }
            }
        }
        __syncthreads();
    }

    l0 += __shfl_xor_sync(~0u, l0, 1); l0 += __shfl_xor_sync(~0u, l0, 2);
    l1 += __shfl_xor_sync(~0u, l1, 1); l1 += __shfl_xor_sync(~0u, l1, 2);
    float i0 = 1.f / l0, i1 = 1.f / l1;
    int r0 = qb0 + wid*16 + (lane >> 2), r1 = r0 + 8;
    #pragma unroll
    for (int j = 0; j < 8; j++) {
        int col = h*64 + j*8 + (lane & 3)*2;
        *(uint32_t*)(O + (size_t)(n*LSEQ + r0)*DMOD + col) = packh2(accO[j][0]*i0, accO[j][1]*i0);
        *(uint32_t*)(O + (size_t)(n*LSEQ + r1)*DMOD + col) = packh2(accO[j][2]*i1, accO[j][3]*i1);
    }
}

// ===================== fused residual + LayerNorm ===========================
template<bool EMIT16>
__global__ void ln_kernel(const __half* __restrict__ x, const float* __restrict__ res,
                          const float* __restrict__ g, const float* __restrict__ b,
                          float* __restrict__ out, __half* __restrict__ o16)
{
    const int row = blockIdx.x;
    const int tid = threadIdx.x;           // 256
    const uint2 xh = ((const uint2*)(x + (size_t)row*DMOD))[tid];
    const float4 rv = ((const float4*)(res + (size_t)row*DMOD))[tid];
    __half2 x01 = *(const __half2*)&xh.x;
    __half2 x23 = *(const __half2*)&xh.y;
    float v0 = __half2float(__low2half(x01))  + rv.x;
    float v1 = __half2float(__high2half(x01)) + rv.y;
    float v2 = __half2float(__low2half(x23))  + rv.z;
    float v3 = __half2float(__high2half(x23)) + rv.w;

    float s  = v0 + v1 + v2 + v3;
    float ss = v0*v0 + v1*v1 + v2*v2 + v3*v3;

    __shared__ float red0[8], red1[8];
    #pragma unroll
    for (int o = 16; o > 0; o >>= 1) {
        s  += __shfl_xor_sync(0xFFFFFFFFu, s,  o);
        ss += __shfl_xor_sync(0xFFFFFFFFu, ss, o);
    }
    if ((tid & 31) == 0) { red0[tid>>5] = s; red1[tid>>5] = ss; }
    __syncthreads();
    float S = 0.f, SS = 0.f;
    #pragma unroll
    for (int w = 0; w < 8; w++) { S += red0[w]; SS += red1[w]; }

    const float mu   = S * (1.0f/DMOD);
    const float var  = SS * (1.0f/DMOD) - mu*mu;
    const float rstd = rsqrtf(var + 1e-5f);

    const float4 gv = ((const float4*)g)[tid];
    const float4 bv = ((const float4*)b)[tid];
    float4 o;
    o.x = (v0 - mu)*rstd*gv.x + bv.x;
    o.y = (v1 - mu)*rstd*gv.y + bv.y;
    o.z = (v2 - mu)*rstd*gv.z + bv.z;
    o.w = (v3 - mu)*rstd*gv.w + bv.w;
    ((float4*)(out + (size_t)row*DMOD))[tid] = o;
    if (EMIT16) {
        *(uint2*)(o16 + (size_t)row*DMOD + tid*4) =
            make_uint2(packh2(o.x, o.y), packh2(o.z, o.w));
    }
}

// ================================ launch ====================================
extern "C" void kernel_launch(void* const* d_in, const int* in_sizes, int n_in,
                              void* d_out, int out_size)
{
    const float* queries = (const float*)d_in[0];
    const float* keys    = (const float*)d_in[1];
    const float* values  = (const float*)d_in[2];
    const int*   mask    = (const int*  )d_in[3];
    const float* fc_w    = (const float*)d_in[4];
    const float* fc_b    = (const float*)d_in[5];
    const float* ln1_g   = (const float*)d_in[6];
    const float* ln1_b   = (const float*)d_in[7];
    const float* ff_w1   = (const float*)d_in[8];
    const float* ff_b1   = (const float*)d_in[9];
    const float* ff_w2   = (const float*)d_in[10];
    const float* ff_b2   = (const float*)d_in[11];
    const float* ln2_g   = (const float*)d_in[12];
    const float* ln2_b   = (const float*)d_in[13];
    float* out = (float*)d_out;

    __half *qh, *kh, *vh, *fcw, *w1, *w2, *at, *x1f, *ff, *tmp16;
    float *x1, *mb;
    cudaGetSymbolAddress((void**)&qh,    g_qh);
    cudaGetSymbolAddress((void**)&kh,    g_kh);
    cudaGetSymbolAddress((void**)&vh,    g_vh);
    cudaGetSymbolAddress((void**)&fcw,   g_fcw);
    cudaGetSymbolAddress((void**)&w1,    g_w1);
    cudaGetSymbolAddress((void**)&w2,    g_w2);
    cudaGetSymbolAddress((void**)&at,    g_at);
    cudaGetSymbolAddress((void**)&x1f,   g_x1f);
    cudaGetSymbolAddress((void**)&ff,    g_ff);
    cudaGetSymbolAddress((void**)&tmp16, g_tmp16);
    cudaGetSymbolAddress((void**)&x1,    g_x1);
    cudaGetSymbolAddress((void**)&mb,    g_mb);

    cudaFuncSetAttribute(gemm_cp<0>, cudaFuncAttributeMaxDynamicSharedMemorySize, GSMEM);
    cudaFuncSetAttribute(gemm_cp<1>, cudaFuncAttributeMaxDynamicSharedMemorySize, GSMEM);
    cudaFuncSetAttribute(attn_cp,    cudaFuncAttributeMaxDynamicSharedMemorySize, ASMEM);

    // 0) preps (single stream)
    prep_qkv<<<4112, 256>>>((const float4*)queries, (const float4*)keys,
                            (const float4*)values, mask, qh, kh, vh, mb);
    prep_w<<<9216, 256>>>(fc_w, ff_w1, ff_w2, fcw, w1, w2);

    // 1) attention -> fp16
    attn_cp<<<dim3(LSEQ/128, NHEAD, NB), 256, ASMEM>>>(qh, kh, vh, mb, at);
    // 2) fc projection -> fp16 tmp
    gemm_cp<0><<<dim3(DMOD/128, NTOK/128), 256, GSMEM>>>(at, fcw, fc_b,
                                                         tmp16, NTOK, DMOD, DMOD);
    // 3) x1 = LN(tmp + queries) -> fp32 + fp16
    ln_kernel<true><<<NTOK, 256>>>(tmp16, queries, ln1_g, ln1_b, x1, x1f);
    // 4) ff = relu(x1 @ w1 + b1) -> fp16
    gemm_cp<1><<<dim3(DFF/128, NTOK/128), 256, GSMEM>>>(x1f, w1, ff_b1,
                                                        ff, NTOK, DFF, DMOD);
    // 5) tmp = ff @ w2 + b2 -> fp16
    gemm_cp<0><<<dim3(DMOD/128, NTOK/128), 256, GSMEM>>>(ff, w2, ff_b2,
                                                         tmp16, NTOK, DMOD, DFF);
    // 6) out = LN(tmp + x1)
    ln_kernel<false><<<NTOK, 256>>>(tmp16, x1, ln2_g, ln2_b, out, nullptr);
}